// round 1
// baseline (speedup 1.0000x reference)
#include <cuda_runtime.h>

#define NN   50000
#define NE   600000
#define ETOT 650000          // NE + NN self loops
#define CH   128
#define NL   6
#define NEG  0.2f
#define INVN (1.0f/50000.0f)
#define NBLK_SCAN 196        // ceil(50000/256)

// ---------------- scratch (static __device__ arrays, no allocation) ----------------
__device__ float d_bufA[(size_t)NN*CH];
__device__ float d_bufB[(size_t)NN*CH];
__device__ float d_bufG[(size_t)NN*CH];
__device__ float d_hlin[(size_t)NN*CH];
__device__ float d_asrc[NN*4];
__device__ float d_adst[NN*4];
__device__ int   d_deg[NN];
__device__ int   d_rowptr[NN+1];
__device__ int   d_colsrc[ETOT];
__device__ int   d_bsums[256];
__device__ float d_bnsum[NL*CH];
__device__ float d_bnsq[NL*CH];

// ---------------- helpers ----------------
__device__ __forceinline__ float leaky(float x) {
    return fmaxf(x, 0.f) + NEG * fminf(x, 0.f);
}

// ---------------- init ----------------
__global__ void k_zero() {
    int i = blockIdx.x * blockDim.x + threadIdx.x;
    if (i < NN) d_deg[i] = 0;
    if (i < NL*CH) { d_bnsum[i] = 0.f; d_bnsq[i] = 0.f; }
}

// ---------------- CSR build (by destination) ----------------
__global__ void k_count(const int* __restrict__ ei) {
    int e = blockIdx.x * blockDim.x + threadIdx.x;
    if (e >= ETOT) return;
    int dst = (e < NE) ? ei[NE + e] : (e - NE);
    atomicAdd(&d_deg[dst], 1);
}

__global__ void k_scan_reduce() {
    __shared__ int s[256];
    int i = blockIdx.x * 256 + threadIdx.x;
    s[threadIdx.x] = (i < NN) ? d_deg[i] : 0;
    __syncthreads();
    for (int off = 128; off; off >>= 1) {
        if (threadIdx.x < off) s[threadIdx.x] += s[threadIdx.x + off];
        __syncthreads();
    }
    if (threadIdx.x == 0) d_bsums[blockIdx.x] = s[0];
}

__global__ void k_scan_mid() {
    if (threadIdx.x == 0) {
        int acc = 0;
        for (int b = 0; b < NBLK_SCAN; b++) {
            int v = d_bsums[b]; d_bsums[b] = acc; acc += v;
        }
        d_rowptr[NN] = ETOT;
    }
}

__global__ void k_scan_write() {
    __shared__ int s[256];
    int i = blockIdx.x * 256 + threadIdx.x;
    int v = (i < NN) ? d_deg[i] : 0;
    s[threadIdx.x] = v;
    __syncthreads();
    for (int off = 1; off < 256; off <<= 1) {
        int t = (threadIdx.x >= off) ? s[threadIdx.x - off] : 0;
        __syncthreads();
        s[threadIdx.x] += t;
        __syncthreads();
    }
    if (i < NN) {
        d_rowptr[i] = d_bsums[blockIdx.x] + s[threadIdx.x] - v;  // exclusive
        d_deg[i] = 0;                                            // reuse as cursor
    }
}

__global__ void k_scatter(const int* __restrict__ ei) {
    int e = blockIdx.x * blockDim.x + threadIdx.x;
    if (e >= ETOT) return;
    int src, dst;
    if (e < NE) { src = ei[e]; dst = ei[NE + e]; }
    else        { src = dst = e - NE; }
    int pos = d_rowptr[dst] + atomicAdd(&d_deg[dst], 1);
    d_colsrc[pos] = src;
}

// ---------------- GEMM: h_lin = A[NN,128] @ W[128,128] ----------------
// 256 threads, tile 64(M) x 128(N), K chunks of 32, 4x8 micro-tile.
__global__ void k_gemm(const float* __restrict__ A, const float* __restrict__ W) {
    __shared__ float As[64][33];
    __shared__ float Bs[32][128];
    int tid = threadIdx.x;
    int bm = blockIdx.x * 64;
    int tx = tid & 15;        // n: tx*8
    int ty = tid >> 4;        // m: ty*4
    float acc[4][8];
#pragma unroll
    for (int i = 0; i < 4; i++)
#pragma unroll
        for (int j = 0; j < 8; j++) acc[i][j] = 0.f;

    int a_row = tid >> 3;            // 0..31
    int a_k4  = (tid & 7) << 2;      // 0,4,...,28
    int b_row = tid >> 5;            // 0..7
    int b_c4  = (tid & 31) << 2;     // 0..124

    for (int k0 = 0; k0 < 128; k0 += 32) {
#pragma unroll
        for (int s = 0; s < 2; s++) {
            int r = a_row + s * 32;
            int gr = bm + r;
            float4 v = make_float4(0.f, 0.f, 0.f, 0.f);
            if (gr < NN) v = *(const float4*)(A + (size_t)gr * 128 + k0 + a_k4);
            As[r][a_k4 + 0] = v.x; As[r][a_k4 + 1] = v.y;
            As[r][a_k4 + 2] = v.z; As[r][a_k4 + 3] = v.w;
        }
#pragma unroll
        for (int s = 0; s < 4; s++) {
            int kr = b_row + s * 8;
            *(float4*)&Bs[kr][b_c4] = *(const float4*)(W + (size_t)(k0 + kr) * 128 + b_c4);
        }
        __syncthreads();
#pragma unroll
        for (int kk = 0; kk < 32; kk++) {
            float a0 = As[ty*4+0][kk], a1 = As[ty*4+1][kk];
            float a2 = As[ty*4+2][kk], a3 = As[ty*4+3][kk];
            float4 b0 = *(float4*)&Bs[kk][tx*8];
            float4 b1 = *(float4*)&Bs[kk][tx*8+4];
            float bb[8] = {b0.x,b0.y,b0.z,b0.w,b1.x,b1.y,b1.z,b1.w};
#pragma unroll
            for (int j = 0; j < 8; j++) {
                acc[0][j] += a0 * bb[j];
                acc[1][j] += a1 * bb[j];
                acc[2][j] += a2 * bb[j];
                acc[3][j] += a3 * bb[j];
            }
        }
        __syncthreads();
    }
#pragma unroll
    for (int i = 0; i < 4; i++) {
        int gr = bm + ty*4 + i;
        if (gr < NN) {
            float4 o0 = make_float4(acc[i][0], acc[i][1], acc[i][2], acc[i][3]);
            float4 o1 = make_float4(acc[i][4], acc[i][5], acc[i][6], acc[i][7]);
            *(float4*)(d_hlin + (size_t)gr * 128 + tx*8)     = o0;
            *(float4*)(d_hlin + (size_t)gr * 128 + tx*8 + 4) = o1;
        }
    }
}

// ---------------- per-node attention logits ----------------
// warp per node; lane l owns channels 4l..4l+3 (head = l>>3, att flat idx = 4l)
__global__ void k_alpha(const float* __restrict__ as_l, const float* __restrict__ ad_l) {
    int tid = threadIdx.x;
    int w = tid >> 5, lane = tid & 31;
    int node = blockIdx.x * 8 + w;                 // 6250*8 = 50000 exact
    float4 h = *(const float4*)(d_hlin + (size_t)node * 128 + lane * 4);
    float4 a = *(const float4*)(as_l + lane * 4);
    float4 b = *(const float4*)(ad_l + lane * 4);
    float ps = h.x*a.x + h.y*a.y + h.z*a.z + h.w*a.w;
    float pd = h.x*b.x + h.y*b.y + h.z*b.z + h.w*b.w;
    ps += __shfl_down_sync(0xffffffffu, ps, 4, 8);
    ps += __shfl_down_sync(0xffffffffu, ps, 2, 8);
    ps += __shfl_down_sync(0xffffffffu, ps, 1, 8);
    pd += __shfl_down_sync(0xffffffffu, pd, 4, 8);
    pd += __shfl_down_sync(0xffffffffu, pd, 2, 8);
    pd += __shfl_down_sync(0xffffffffu, pd, 1, 8);
    if ((lane & 7) == 0) {
        d_asrc[node * 4 + (lane >> 3)] = ps;
        d_adst[node * 4 + (lane >> 3)] = pd;
    }
}

// ---------------- GAT aggregation (warp per dst) + BN stats ----------------
__global__ void k_agg(const float* __restrict__ bias_l,
                      float* __restrict__ bnsum, float* __restrict__ bnsq) {
    __shared__ int   s_src[8][32];
    __shared__ float s_w[8][128];
    __shared__ float s_s1[128], s_s2[128];
    int tid = threadIdx.x;
    if (tid < 128) { s_s1[tid] = 0.f; s_s2[tid] = 0.f; }
    __syncthreads();

    int w = tid >> 5, lane = tid & 31;
    int dst = blockIdx.x * 8 + w;                  // exact coverage
    int beg = d_rowptr[dst], end = d_rowptr[dst + 1];
    int head = lane >> 3;
    float4 ad = *(const float4*)(d_adst + dst * 4);

    // pass 1: per-head max over segment
    float4 em = make_float4(-1e30f, -1e30f, -1e30f, -1e30f);
    for (int base = beg; base < end; base += 32) {
        int idx = base + lane;
        if (idx < end) {
            int s = d_colsrc[idx];
            float4 a = *(const float4*)(d_asrc + s * 4);
            em.x = fmaxf(em.x, leaky(a.x + ad.x));
            em.y = fmaxf(em.y, leaky(a.y + ad.y));
            em.z = fmaxf(em.z, leaky(a.z + ad.z));
            em.w = fmaxf(em.w, leaky(a.w + ad.w));
        }
    }
#pragma unroll
    for (int d = 16; d; d >>= 1) {
        em.x = fmaxf(em.x, __shfl_xor_sync(0xffffffffu, em.x, d));
        em.y = fmaxf(em.y, __shfl_xor_sync(0xffffffffu, em.y, d));
        em.z = fmaxf(em.z, __shfl_xor_sync(0xffffffffu, em.z, d));
        em.w = fmaxf(em.w, __shfl_xor_sync(0xffffffffu, em.w, d));
    }

    // pass 2: exp weights + feature accumulate
    float4 ds  = make_float4(0.f, 0.f, 0.f, 0.f);
    float4 acc = make_float4(0.f, 0.f, 0.f, 0.f);
    for (int base = beg; base < end; base += 32) {
        int idx = base + lane;
        int nE = min(32, end - base);
        if (idx < end) {
            int s = d_colsrc[idx];
            float4 a = *(const float4*)(d_asrc + s * 4);
            float4 wv;
            wv.x = __expf(leaky(a.x + ad.x) - em.x);
            wv.y = __expf(leaky(a.y + ad.y) - em.y);
            wv.z = __expf(leaky(a.z + ad.z) - em.z);
            wv.w = __expf(leaky(a.w + ad.w) - em.w);
            ds.x += wv.x; ds.y += wv.y; ds.z += wv.z; ds.w += wv.w;
            s_src[w][lane] = s;
            *(float4*)&s_w[w][lane * 4] = wv;
        }
        __syncwarp();
        for (int j = 0; j < nE; j++) {
            int s = s_src[w][j];
            float wt = s_w[w][j * 4 + head];
            float4 hv = *(const float4*)(d_hlin + (size_t)s * 128 + lane * 4);
            acc.x += hv.x * wt; acc.y += hv.y * wt;
            acc.z += hv.z * wt; acc.w += hv.w * wt;
        }
        __syncwarp();
    }
#pragma unroll
    for (int d = 16; d; d >>= 1) {
        ds.x += __shfl_xor_sync(0xffffffffu, ds.x, d);
        ds.y += __shfl_xor_sync(0xffffffffu, ds.y, d);
        ds.z += __shfl_xor_sync(0xffffffffu, ds.z, d);
        ds.w += __shfl_xor_sync(0xffffffffu, ds.w, d);
    }
    float dn = (head == 0) ? ds.x : (head == 1) ? ds.y : (head == 2) ? ds.z : ds.w;
    float inv = 1.0f / dn;
    float4 b4 = *(const float4*)(bias_l + lane * 4);
    float4 o = make_float4(acc.x * inv + b4.x, acc.y * inv + b4.y,
                           acc.z * inv + b4.z, acc.w * inv + b4.w);
    *(float4*)(d_bufG + (size_t)dst * 128 + lane * 4) = o;

    // BN partial sums (channel depends only on lane)
    int c0 = lane * 4;
    atomicAdd(&s_s1[c0+0], o.x); atomicAdd(&s_s1[c0+1], o.y);
    atomicAdd(&s_s1[c0+2], o.z); atomicAdd(&s_s1[c0+3], o.w);
    atomicAdd(&s_s2[c0+0], o.x*o.x); atomicAdd(&s_s2[c0+1], o.y*o.y);
    atomicAdd(&s_s2[c0+2], o.z*o.z); atomicAdd(&s_s2[c0+3], o.w*o.w);
    __syncthreads();
    if (tid < 128) {
        atomicAdd(&bnsum[tid], s_s1[tid]);
        atomicAdd(&bnsq[tid],  s_s2[tid]);
    }
}

// ---------------- BN apply + optional residual + ReLU ----------------
__global__ void k_bn(const float* __restrict__ gamma, const float* __restrict__ beta,
                     const float* __restrict__ bsum,  const float* __restrict__ bsq,
                     const float* __restrict__ skip,  float* __restrict__ out) {
    __shared__ float sc[128], sh[128];
    int tid = threadIdx.x;
    if (tid < 128) {
        float mu  = bsum[tid] * INVN;
        float var = bsq[tid] * INVN - mu * mu;
        float r = rsqrtf(var + 1e-5f);
        float g = gamma[tid] * r;
        sc[tid] = g;
        sh[tid] = beta[tid] - g * mu;
    }
    __syncthreads();
    size_t g4 = (size_t)blockIdx.x * 256 + tid;   // float4 index; 6250*256 = 1.6M exact
    int q = (int)(g4 & 31) * 4;
    float4 v = ((const float4*)d_bufG)[g4];
    float4 y;
    y.x = v.x * sc[q+0] + sh[q+0];
    y.y = v.y * sc[q+1] + sh[q+1];
    y.z = v.z * sc[q+2] + sh[q+2];
    y.w = v.w * sc[q+3] + sh[q+3];
    if (skip) {
        float4 s4 = ((const float4*)skip)[g4];
        y.x += s4.x; y.y += s4.y; y.z += s4.z; y.w += s4.w;
    }
    y.x = fmaxf(y.x, 0.f); y.y = fmaxf(y.y, 0.f);
    y.z = fmaxf(y.z, 0.f); y.w = fmaxf(y.w, 0.f);
    ((float4*)out)[g4] = y;
}

// ---------------- launch ----------------
extern "C" void kernel_launch(void* const* d_in, const int* in_sizes, int n_in,
                              void* d_out, int out_size) {
    const float* x       = (const float*)d_in[0];
    const int*   ei      = (const int*)  d_in[1];
    const float* Ws      = (const float*)d_in[2];
    const float* att_src = (const float*)d_in[3];
    const float* att_dst = (const float*)d_in[4];
    const float* biases  = (const float*)d_in[5];
    const float* gammas  = (const float*)d_in[6];
    const float* betas   = (const float*)d_in[7];
    float* out = (float*)d_out;

    void *pA, *pB, *pSum, *pSq;
    cudaGetSymbolAddress(&pA, d_bufA);
    cudaGetSymbolAddress(&pB, d_bufB);
    cudaGetSymbolAddress(&pSum, d_bnsum);
    cudaGetSymbolAddress(&pSq,  d_bnsq);
    float* A = (float*)pA;
    float* B = (float*)pB;
    float* bnsum = (float*)pSum;
    float* bnsq  = (float*)pSq;

    // CSR build + init (once per launch)
    k_zero<<<NBLK_SCAN, 256>>>();
    k_count<<<(ETOT + 255) / 256, 256>>>(ei);
    k_scan_reduce<<<NBLK_SCAN, 256>>>();
    k_scan_mid<<<1, 32>>>();
    k_scan_write<<<NBLK_SCAN, 256>>>();
    k_scatter<<<(ETOT + 255) / 256, 256>>>(ei);

    // layer plumbing: stem(L0,L1) -> block0(L2,L3,+skip) -> block1(L4,L5,+skip)
    const float* ins[NL]   = { x, A, B, A, A, B };
    float*       outs[NL]  = { A, B, A, A, B, out };
    const float* skips[NL] = { 0, 0, 0, B, 0, A };

    for (int l = 0; l < NL; l++) {
        k_gemm<<<(NN + 63) / 64, 256>>>(ins[l], Ws + (size_t)l * 128 * 128);
        k_alpha<<<NN / 8, 256>>>(att_src + l * 128, att_dst + l * 128);
        k_agg<<<NN / 8, 256>>>(biases + l * 128, bnsum + l * 128, bnsq + l * 128);
        k_bn<<<NN / 8, 256>>>(gammas + l * 128, betas + l * 128,
                              bnsum + l * 128, bnsq + l * 128,
                              skips[l], outs[l]);
    }
}

// round 3
// speedup vs baseline: 1.2094x; 1.2094x over previous
#include <cuda_runtime.h>
#include <cstdint>

#define NN   50000
#define NE   600000
#define ETOT 650000          // NE + NN self loops
#define CH   128
#define NL   6
#define NEG  0.2f
#define INVN (1.0f/50000.0f)
#define NBLK_SCAN 196        // ceil(50000/256)
#define GEMM_CTAS 391        // ceil(50000/128)
#define WTOT (NL*128*128)    // 98304

// ---------------- scratch (static __device__ arrays, no allocation) ----------------
__device__ float d_bufA[(size_t)NN*CH];
__device__ float d_bufB[(size_t)NN*CH];
__device__ float d_bufG[(size_t)NN*CH];
__device__ float d_hlin[(size_t)NN*CH];
__device__ float d_asrc[NN*4];
__device__ float d_adst[NN*4];
__device__ int   d_deg[NN];
__device__ int   d_rowptr[NN+1];
__device__ int   d_colsrc[ETOT];
__device__ int   d_bsums[256];
__device__ float d_bnsum[NL*CH];
__device__ float d_bnsq[NL*CH];
// W split into tf32 hi/lo, pre-reordered into the GEMM smem image layout:
// img[l][n*128 + (k>>5)*32 + ((k>>3)&3)*8 + (k&3)*2 + ((k>>2)&1)]
__device__ float d_whi[WTOT];
__device__ float d_wlo[WTOT];

// ---------------- helpers ----------------
__device__ __forceinline__ float leaky(float x) {
    return fmaxf(x, 0.f) + NEG * fminf(x, 0.f);
}
__device__ __forceinline__ uint32_t f2tf32(float x) {
    uint32_t r;
    asm("cvt.rna.tf32.f32 %0, %1;" : "=r"(r) : "f"(x));
    return r;
}
__device__ __forceinline__ void mma8(float* c, uint32_t a0, uint32_t a1,
                                     uint32_t a2, uint32_t a3,
                                     uint32_t b0, uint32_t b1) {
    asm volatile(
        "mma.sync.aligned.m16n8k8.row.col.f32.tf32.tf32.f32 "
        "{%0,%1,%2,%3}, {%4,%5,%6,%7}, {%8,%9}, {%0,%1,%2,%3};"
        : "+f"(c[0]), "+f"(c[1]), "+f"(c[2]), "+f"(c[3])
        : "r"(a0), "r"(a1), "r"(a2), "r"(a3), "r"(b0), "r"(b1));
}

// ---------------- init: zero counters + split/reorder W (once) ----------------
__global__ void k_init(const float* __restrict__ Ws) {
    int i = blockIdx.x * 256 + threadIdx.x;     // grid 384 -> 98304 threads
    if (i < NN) d_deg[i] = 0;
    if (i < NL*CH) { d_bnsum[i] = 0.f; d_bnsq[i] = 0.f; }
    if (i == 0) d_rowptr[NN] = ETOT;
    if (i < WTOT) {
        int l = i >> 14, rem = i & 16383;
        int k = rem >> 7, n = rem & 127;
        float v = Ws[i];
        uint32_t hb = f2tf32(v);
        uint32_t lb = f2tf32(v - __uint_as_float(hb));
        int pos = l * 16384 + n * 128 + ((k >> 5) << 5)
                + (((k >> 3) & 3) << 3) + ((k & 3) << 1) + ((k >> 2) & 1);
        d_whi[pos] = __uint_as_float(hb);
        d_wlo[pos] = __uint_as_float(lb);
    }
}

// ---------------- CSR build (by destination) ----------------
__global__ void k_count(const int* __restrict__ ei) {
    int e = blockIdx.x * blockDim.x + threadIdx.x;
    if (e >= ETOT) return;
    int dst = (e < NE) ? ei[NE + e] : (e - NE);
    atomicAdd(&d_deg[dst], 1);
}

__global__ void k_scan_reduce() {
    __shared__ int s[256];
    int i = blockIdx.x * 256 + threadIdx.x;
    s[threadIdx.x] = (i < NN) ? d_deg[i] : 0;
    __syncthreads();
    for (int off = 128; off; off >>= 1) {
        if (threadIdx.x < off) s[threadIdx.x] += s[threadIdx.x + off];
        __syncthreads();
    }
    if (threadIdx.x == 0) d_bsums[blockIdx.x] = s[0];
}

__global__ void k_scan_write() {
    __shared__ int s[256];
    __shared__ int soff[256];
    int tid = threadIdx.x;
    int i = blockIdx.x * 256 + tid;
    int v = (i < NN) ? d_deg[i] : 0;
    soff[tid] = (tid < blockIdx.x) ? d_bsums[tid] : 0;
    s[tid] = v;
    __syncthreads();
    for (int off = 128; off; off >>= 1) {
        if (tid < off) soff[tid] += soff[tid + off];
        __syncthreads();
    }
    for (int off = 1; off < 256; off <<= 1) {
        int t = (tid >= off) ? s[tid - off] : 0;
        __syncthreads();
        s[tid] += t;
        __syncthreads();
    }
    if (i < NN) {
        d_rowptr[i] = soff[0] + s[tid] - v;
        d_deg[i] = 0;
    }
}

__global__ void k_scatter(const int* __restrict__ ei) {
    int e = blockIdx.x * blockDim.x + threadIdx.x;
    if (e >= ETOT) return;
    int src, dst;
    if (e < NE) { src = ei[e]; dst = ei[NE + e]; }
    else        { src = dst = e - NE; }
    int pos = d_rowptr[dst] + atomicAdd(&d_deg[dst], 1);
    d_colsrc[pos] = src;
}

// ---------------- tensor-core GEMM (mma.sync tf32, 3-term) + fused alpha ----------------
// CTA: 256 thr (8 warps, grid wm=warp>>1 over M, wn=warp&1 over N)
// tile M=128 N=128, K chunks of 32 (4 ksteps of 8).
// smem floats: Ahi[0,5120) Alo[5120,10240) Bhi[10240,15360) Blo[15360,20480)
//              attS[20480,20608) attD[20608,20736)   => 82944 bytes
// A/B stored as paired float2 rows, stride 20 float2 (40 floats):
//   pair (col t, col t+4) at [row*20 + ks*4 + t]
#define GSM_FLOATS 20736
#define GSM_BYTES  82944

__global__ void __launch_bounds__(256, 1)
k_gemm_tc(const float* __restrict__ A, const float* __restrict__ Whi,
          const float* __restrict__ Wlo,
          const float* __restrict__ attS, const float* __restrict__ attD) {
    extern __shared__ float smf[];
    float2* A2h = (float2*)smf;
    float2* A2l = (float2*)(smf + 5120);
    float2* B2h = (float2*)(smf + 10240);
    float2* B2l = (float2*)(smf + 15360);
    float*  sAt = smf + 20480;
    float*  dAt = smf + 20608;

    int tid = threadIdx.x;
    int lane = tid & 31, g = lane >> 2, t = lane & 3;
    int w = tid >> 5, wm = w >> 1, wn = w & 1;
    int bm = blockIdx.x * 128;

    if (tid < 128) sAt[tid] = attS[tid];
    else           dAt[tid - 128] = attD[tid - 128];

    float cfr[2][8][4];
#pragma unroll
    for (int i = 0; i < 2; i++)
#pragma unroll
        for (int j = 0; j < 8; j++)
#pragma unroll
            for (int q = 0; q < 4; q++) cfr[i][j][q] = 0.f;

    for (int kc = 0; kc < 4; kc++) {
        // ---- stage A chunk [128 x 32] -> hi/lo paired ----
#pragma unroll
        for (int it = 0; it < 4; it++) {
            int f = tid + it * 256;          // 1024 float4s
            int row = f >> 3, j = f & 7;
            int gr = bm + row;
            float4 v = make_float4(0.f, 0.f, 0.f, 0.f);
            if (gr < NN) v = *(const float4*)(A + (size_t)gr * 128 + kc * 32 + j * 4);
            int ks = j >> 1, half = j & 1;
            float* ph = smf + row * 40 + ks * 8 + half;          // hi
            float* pl = ph + 5120;                               // lo
            float vv[4] = {v.x, v.y, v.z, v.w};
#pragma unroll
            for (int cc = 0; cc < 4; cc++) {
                uint32_t hb = f2tf32(vv[cc]);
                ph[cc * 2] = __uint_as_float(hb);
                pl[cc * 2] = __uint_as_float(f2tf32(vv[cc] - __uint_as_float(hb)));
            }
        }
        // ---- stage B chunk: pre-imaged, straight float4 copy ----
#pragma unroll
        for (int it = 0; it < 4; it++) {
            int f = tid + it * 256;          // 1024 float4s
            int n = f >> 3, q = f & 7;
            int gi = n * 32 + kc * 8 + q;    // float4 index into layer image
            float4 h4 = ((const float4*)Whi)[gi];
            float4 l4 = ((const float4*)Wlo)[gi];
            *(float4*)(smf + 10240 + n * 40 + q * 4) = h4;
            *(float4*)(smf + 15360 + n * 40 + q * 4) = l4;
        }
        __syncthreads();

        // ---- compute 4 ksteps ----
#pragma unroll
        for (int ks = 0; ks < 4; ks++) {
            float2 ah[2][2], al[2][2];
#pragma unroll
            for (int mt = 0; mt < 2; mt++) {
                int r0 = wm * 32 + mt * 16 + g;
                ah[mt][0] = A2h[r0 * 20 + ks * 4 + t];
                ah[mt][1] = A2h[(r0 + 8) * 20 + ks * 4 + t];
                al[mt][0] = A2l[r0 * 20 + ks * 4 + t];
                al[mt][1] = A2l[(r0 + 8) * 20 + ks * 4 + t];
            }
#pragma unroll
            for (int nt = 0; nt < 8; nt++) {
                int n = wn * 64 + nt * 8 + g;
                float2 bh = B2h[n * 20 + ks * 4 + t];
                float2 bl = B2l[n * 20 + ks * 4 + t];
                uint32_t bh0 = __float_as_uint(bh.x), bh1 = __float_as_uint(bh.y);
                uint32_t bl0 = __float_as_uint(bl.x), bl1 = __float_as_uint(bl.y);
#pragma unroll
                for (int mt = 0; mt < 2; mt++) {
                    uint32_t a0 = __float_as_uint(ah[mt][0].x);
                    uint32_t a1 = __float_as_uint(ah[mt][1].x);
                    uint32_t a2 = __float_as_uint(ah[mt][0].y);
                    uint32_t a3 = __float_as_uint(ah[mt][1].y);
                    mma8(cfr[mt][nt], a0, a1, a2, a3, bh0, bh1);   // hi*hi
                    mma8(cfr[mt][nt], a0, a1, a2, a3, bl0, bl1);   // hi*lo
                    uint32_t l0 = __float_as_uint(al[mt][0].x);
                    uint32_t l1 = __float_as_uint(al[mt][1].x);
                    uint32_t l2 = __float_as_uint(al[mt][0].y);
                    uint32_t l3 = __float_as_uint(al[mt][1].y);
                    mma8(cfr[mt][nt], l0, l1, l2, l3, bh0, bh1);   // lo*hi
                }
            }
        }
        __syncthreads();
    }

    // ---- epilogue: store h + fused per-head alpha dots ----
#pragma unroll
    for (int mt = 0; mt < 2; mt++) {
#pragma unroll
        for (int rr = 0; rr < 2; rr++) {
            int row = bm + wm * 32 + mt * 16 + rr * 8 + g;
            float psA = 0.f, psB = 0.f, pdA = 0.f, pdB = 0.f;
#pragma unroll
            for (int nt = 0; nt < 8; nt++) {
                float c0 = cfr[mt][nt][rr * 2 + 0];
                float c1 = cfr[mt][nt][rr * 2 + 1];
                int col0 = wn * 64 + nt * 8 + 2 * t;
                if (row < NN)
                    *(float2*)(d_hlin + (size_t)row * 128 + col0) = make_float2(c0, c1);
                float s0 = sAt[col0], s1 = sAt[col0 + 1];
                float q0 = dAt[col0], q1 = dAt[col0 + 1];
                if (nt < 4) { psA += c0 * s0 + c1 * s1; pdA += c0 * q0 + c1 * q1; }
                else        { psB += c0 * s0 + c1 * s1; pdB += c0 * q0 + c1 * q1; }
            }
            psA += __shfl_down_sync(0xffffffffu, psA, 2, 4);
            psA += __shfl_down_sync(0xffffffffu, psA, 1, 4);
            psB += __shfl_down_sync(0xffffffffu, psB, 2, 4);
            psB += __shfl_down_sync(0xffffffffu, psB, 1, 4);
            pdA += __shfl_down_sync(0xffffffffu, pdA, 2, 4);
            pdA += __shfl_down_sync(0xffffffffu, pdA, 1, 4);
            pdB += __shfl_down_sync(0xffffffffu, pdB, 2, 4);
            pdB += __shfl_down_sync(0xffffffffu, pdB, 1, 4);
            if (t == 0 && row < NN) {
                int h0 = wn * 2;
                d_asrc[row * 4 + h0]     = psA;
                d_asrc[row * 4 + h0 + 1] = psB;
                d_adst[row * 4 + h0]     = pdA;
                d_adst[row * 4 + h0 + 1] = pdB;
            }
        }
    }
}

// ---------------- GAT aggregation (warp per dst) + BN stats ----------------
__global__ void k_agg(const float* __restrict__ bias_l,
                      float* __restrict__ bnsum, float* __restrict__ bnsq) {
    __shared__ int   s_src[8][32];
    __shared__ float s_w[8][128];
    __shared__ float s_s1[128], s_s2[128];
    int tid = threadIdx.x;
    if (tid < 128) { s_s1[tid] = 0.f; s_s2[tid] = 0.f; }
    __syncthreads();

    int w = tid >> 5, lane = tid & 31;
    int dst = blockIdx.x * 8 + w;
    int beg = d_rowptr[dst], end = d_rowptr[dst + 1];
    int head = lane >> 3;
    float4 ad = *(const float4*)(d_adst + dst * 4);

    float4 em = make_float4(-1e30f, -1e30f, -1e30f, -1e30f);
    for (int base = beg; base < end; base += 32) {
        int idx = base + lane;
        if (idx < end) {
            int s = d_colsrc[idx];
            float4 a = *(const float4*)(d_asrc + s * 4);
            em.x = fmaxf(em.x, leaky(a.x + ad.x));
            em.y = fmaxf(em.y, leaky(a.y + ad.y));
            em.z = fmaxf(em.z, leaky(a.z + ad.z));
            em.w = fmaxf(em.w, leaky(a.w + ad.w));
        }
    }
#pragma unroll
    for (int d = 16; d; d >>= 1) {
        em.x = fmaxf(em.x, __shfl_xor_sync(0xffffffffu, em.x, d));
        em.y = fmaxf(em.y, __shfl_xor_sync(0xffffffffu, em.y, d));
        em.z = fmaxf(em.z, __shfl_xor_sync(0xffffffffu, em.z, d));
        em.w = fmaxf(em.w, __shfl_xor_sync(0xffffffffu, em.w, d));
    }

    float4 ds  = make_float4(0.f, 0.f, 0.f, 0.f);
    float4 acc = make_float4(0.f, 0.f, 0.f, 0.f);
    for (int base = beg; base < end; base += 32) {
        int idx = base + lane;
        int nE = min(32, end - base);
        if (idx < end) {
            int s = d_colsrc[idx];
            float4 a = *(const float4*)(d_asrc + s * 4);
            float4 wv;
            wv.x = __expf(leaky(a.x + ad.x) - em.x);
            wv.y = __expf(leaky(a.y + ad.y) - em.y);
            wv.z = __expf(leaky(a.z + ad.z) - em.z);
            wv.w = __expf(leaky(a.w + ad.w) - em.w);
            ds.x += wv.x; ds.y += wv.y; ds.z += wv.z; ds.w += wv.w;
            s_src[w][lane] = s;
            *(float4*)&s_w[w][lane * 4] = wv;
        }
        __syncwarp();
        int j = 0;
        const float* hb = d_hlin + lane * 4;
        for (; j + 4 <= nE; j += 4) {
            int s0 = s_src[w][j],   s1 = s_src[w][j+1];
            int s2 = s_src[w][j+2], s3 = s_src[w][j+3];
            float w0 = s_w[w][(j)*4+head],   w1 = s_w[w][(j+1)*4+head];
            float w2 = s_w[w][(j+2)*4+head], w3 = s_w[w][(j+3)*4+head];
            float4 h0 = *(const float4*)(hb + (size_t)s0 * 128);
            float4 h1 = *(const float4*)(hb + (size_t)s1 * 128);
            float4 h2 = *(const float4*)(hb + (size_t)s2 * 128);
            float4 h3 = *(const float4*)(hb + (size_t)s3 * 128);
            acc.x += h0.x*w0 + h1.x*w1 + h2.x*w2 + h3.x*w3;
            acc.y += h0.y*w0 + h1.y*w1 + h2.y*w2 + h3.y*w3;
            acc.z += h0.z*w0 + h1.z*w1 + h2.z*w2 + h3.z*w3;
            acc.w += h0.w*w0 + h1.w*w1 + h2.w*w2 + h3.w*w3;
        }
        for (; j < nE; j++) {
            int s = s_src[w][j];
            float wt = s_w[w][j * 4 + head];
            float4 hv = *(const float4*)(hb + (size_t)s * 128);
            acc.x += hv.x * wt; acc.y += hv.y * wt;
            acc.z += hv.z * wt; acc.w += hv.w * wt;
        }
        __syncwarp();
    }
#pragma unroll
    for (int d = 16; d; d >>= 1) {
        ds.x += __shfl_xor_sync(0xffffffffu, ds.x, d);
        ds.y += __shfl_xor_sync(0xffffffffu, ds.y, d);
        ds.z += __shfl_xor_sync(0xffffffffu, ds.z, d);
        ds.w += __shfl_xor_sync(0xffffffffu, ds.w, d);
    }
    float dn = (head == 0) ? ds.x : (head == 1) ? ds.y : (head == 2) ? ds.z : ds.w;
    float inv = 1.0f / dn;
    float4 b4 = *(const float4*)(bias_l + lane * 4);
    float4 o = make_float4(acc.x * inv + b4.x, acc.y * inv + b4.y,
                           acc.z * inv + b4.z, acc.w * inv + b4.w);
    *(float4*)(d_bufG + (size_t)dst * 128 + lane * 4) = o;

    int c0 = lane * 4;
    atomicAdd(&s_s1[c0+0], o.x); atomicAdd(&s_s1[c0+1], o.y);
    atomicAdd(&s_s1[c0+2], o.z); atomicAdd(&s_s1[c0+3], o.w);
    atomicAdd(&s_s2[c0+0], o.x*o.x); atomicAdd(&s_s2[c0+1], o.y*o.y);
    atomicAdd(&s_s2[c0+2], o.z*o.z); atomicAdd(&s_s2[c0+3], o.w*o.w);
    __syncthreads();
    if (tid < 128) {
        atomicAdd(&bnsum[tid], s_s1[tid]);
        atomicAdd(&bnsq[tid],  s_s2[tid]);
    }
}

// ---------------- BN apply + optional residual + ReLU ----------------
__global__ void k_bn(const float* __restrict__ gamma, const float* __restrict__ beta,
                     const float* __restrict__ bsum,  const float* __restrict__ bsq,
                     const float* __restrict__ skip,  float* __restrict__ out) {
    __shared__ float sc[128], sh[128];
    int tid = threadIdx.x;
    if (tid < 128) {
        float mu  = bsum[tid] * INVN;
        float var = bsq[tid] * INVN - mu * mu;
        float r = rsqrtf(var + 1e-5f);
        float gg = gamma[tid] * r;
        sc[tid] = gg;
        sh[tid] = beta[tid] - gg * mu;
    }
    __syncthreads();
    size_t g4 = (size_t)blockIdx.x * 256 + tid;
    int q = (int)(g4 & 31) * 4;
    float4 v = ((const float4*)d_bufG)[g4];
    float4 y;
    y.x = v.x * sc[q+0] + sh[q+0];
    y.y = v.y * sc[q+1] + sh[q+1];
    y.z = v.z * sc[q+2] + sh[q+2];
    y.w = v.w * sc[q+3] + sh[q+3];
    if (skip) {
        float4 s4 = ((const float4*)skip)[g4];
        y.x += s4.x; y.y += s4.y; y.z += s4.z; y.w += s4.w;
    }
    y.x = fmaxf(y.x, 0.f); y.y = fmaxf(y.y, 0.f);
    y.z = fmaxf(y.z, 0.f); y.w = fmaxf(y.w, 0.f);
    ((float4*)out)[g4] = y;
}

// ---------------- launch ----------------
extern "C" void kernel_launch(void* const* d_in, const int* in_sizes, int n_in,
                              void* d_out, int out_size) {
    const float* x       = (const float*)d_in[0];
    const int*   ei      = (const int*)  d_in[1];
    const float* Ws      = (const float*)d_in[2];
    const float* att_src = (const float*)d_in[3];
    const float* att_dst = (const float*)d_in[4];
    const float* biases  = (const float*)d_in[5];
    const float* gammas  = (const float*)d_in[6];
    const float* betas   = (const float*)d_in[7];
    float* out = (float*)d_out;

    void *pA, *pB, *pSum, *pSq, *pWh, *pWl;
    cudaGetSymbolAddress(&pA, d_bufA);
    cudaGetSymbolAddress(&pB, d_bufB);
    cudaGetSymbolAddress(&pSum, d_bnsum);
    cudaGetSymbolAddress(&pSq,  d_bnsq);
    cudaGetSymbolAddress(&pWh,  d_whi);
    cudaGetSymbolAddress(&pWl,  d_wlo);
    float* A = (float*)pA;
    float* B = (float*)pB;
    float* bnsum = (float*)pSum;
    float* bnsq  = (float*)pSq;
    float* whi   = (float*)pWh;
    float* wlo   = (float*)pWl;

    cudaFuncSetAttribute(k_gemm_tc, cudaFuncAttributeMaxDynamicSharedMemorySize, GSM_BYTES);

    // launches 0-4; launch 5 = layer-0 GEMM (ncu -s 5 -c 1 profiles it)
    k_init<<<384, 256>>>(Ws);
    k_count<<<(ETOT + 255) / 256, 256>>>(ei);
    k_scan_reduce<<<NBLK_SCAN, 256>>>();
    k_scan_write<<<NBLK_SCAN, 256>>>();
    k_scatter<<<(ETOT + 255) / 256, 256>>>(ei);

    const float* ins[NL]   = { x, A, B, A, A, B };
    float*       outs[NL]  = { A, B, A, A, B, out };
    const float* skips[NL] = { 0, 0, 0, B, 0, A };

    for (int l = 0; l < NL; l++) {
        k_gemm_tc<<<GEMM_CTAS, 256, GSM_BYTES>>>(ins[l],
                                                 whi + (size_t)l * 16384,
                                                 wlo + (size_t)l * 16384,
                                                 att_src + l * 128, att_dst + l * 128);
        k_agg<<<NN / 8, 256>>>(biases + l * 128, bnsum + l * 128, bnsq + l * 128);
        k_bn<<<NN / 8, 256>>>(gammas + l * 128, betas + l * 128,
                              bnsum + l * 128, bnsq + l * 128,
                              skips[l], outs[l]);
    }
}